// round 12
// baseline (speedup 1.0000x reference)
#include <cuda_runtime.h>
#include <cuda_bf16.h>
#include <cstdint>

// ---------------------------------------------------------------------------
// LinearAttention fused:
//   final[b] = M_b @ x[b] + b_out
//   M_b derived from ctx[b,h] = softmax(Wk@x) @ (Wv@x)^T  (32x32 per head)
// K1 (HMMA kv-GEMM + FFMA softexp accum): context partials.
// K2a/b/c: reduce -> ctx -> U -> M.
// K3 (HMMA): final = M_b @ x + b_out, bf16 3-term split, STS.128 fills.
// ---------------------------------------------------------------------------

#define BATCH 16
#define CDIM 128
#define NSP 16384
#define NCHUNKS 32
#define CHUNK 512
#define SUBN 32
#define NSUB 16
#define KPITCH 36

__device__ float g_partA[BATCH * NCHUNKS * 128 * 32];  // [b][ch][hd][e]
__device__ float g_partS[BATCH * NCHUNKS * 128];       // [b][ch][hd]
__device__ float g_ctx[BATCH * 128 * 32];              // [b][hd][e]
__device__ float g_U[BATCH * 128 * 128];               // [b][o][hd]
__device__ float g_M[BATCH * 128 * 128];               // [b][o][c]

// ===========================================================================
// shared helpers
// ===========================================================================
__device__ __forceinline__ uint32_t pack_bf16(__nv_bfloat16 a, __nv_bfloat16 b) {
    __nv_bfloat162 t2{a, b};
    return *(uint32_t*)&t2;
}
__device__ __forceinline__ void bf16_split(float v, __nv_bfloat16& h, __nv_bfloat16& l) {
    h = __float2bfloat16(v);
    l = __float2bfloat16(v - __bfloat162float(h));
}
// pack hi/lo words from a (k-even, k-odd) float pair
__device__ __forceinline__ void pack_pair(float ke, float ko, uint32_t& wh, uint32_t& wl) {
    __nv_bfloat16 h0, l0, h1, l1;
    bf16_split(ke, h0, l0);
    bf16_split(ko, h1, l1);
    wh = pack_bf16(h0, h1);
    wl = pack_bf16(l0, l1);
}
__device__ __forceinline__ void mma16816(float* d, const uint32_t* a, const uint32_t* bf) {
    asm volatile(
        "mma.sync.aligned.m16n8k16.row.col.f32.bf16.bf16.f32 "
        "{%0,%1,%2,%3}, {%4,%5,%6,%7}, {%8,%9}, {%0,%1,%2,%3};"
        : "+f"(d[0]), "+f"(d[1]), "+f"(d[2]), "+f"(d[3])
        : "r"(a[0]), "r"(a[1]), "r"(a[2]), "r"(a[3]), "r"(bf[0]), "r"(bf[1]));
}

// ===========================================================================
// K1: context partials. grid (NCHUNKS, BATCH), 256 threads (8 warps).
// HMMA kv-GEMM (256x32 per subtile, K=128, bf16 3-term split) + FFMA accum.
// smem (uint32 units):
//   W2h/W2l : [kk 0..63][row 0..255] pitch 264   (weights rows 128..383)
//   B2h/B2l : [kk 0..63][n 0..31]   pitch 40
//   ke/vsm  : fp32 [128][32] pitch 36
// ===========================================================================
#define PW 264
#define PB 40
#define K1_W_WORDS (64 * PW)            // 16896
#define K1_B_WORDS (64 * PB)            // 2560
#define K1_KE_OFF  (2 * K1_W_WORDS + 2 * K1_B_WORDS)          // 38912
#define K1_SMEM_WORDS (K1_KE_OFF + 2 * 128 * KPITCH)          // 48128
#define K1_SMEM_BYTES (K1_SMEM_WORDS * 4)                     // 192512

__global__ __launch_bounds__(256, 1) void k1_ctx(const float* __restrict__ x,
                                                 const float* __restrict__ w_qkv) {
    extern __shared__ uint32_t sm4[];
    uint32_t* W2h = sm4;
    uint32_t* W2l = sm4 + K1_W_WORDS;
    uint32_t* B2h = sm4 + 2 * K1_W_WORDS;
    uint32_t* B2l = B2h + K1_B_WORDS;
    float* ke  = (float*)(sm4 + K1_KE_OFF);
    float* vsm = ke + 128 * KPITCH;

    const int t    = threadIdx.x;
    const int wid  = t >> 5;
    const int lane = t & 31;
    const int b    = blockIdx.y;
    const int ch   = blockIdx.x;

    // ---- weight fill: kv rows (w_qkv rows 128..383) -> bf16 hi/lo packed ----
    // task li: kk = li>>6, r4 = (li&63)*4 ; word[j] for rows r4..r4+3 -> STS.128
#pragma unroll
    for (int i = 0; i < 16; i++) {
        int li = t + i * 256;
        int kk = li >> 6;
        int r4 = (li & 63) * 4;
        const float* src = w_qkv + (size_t)(128 + r4) * CDIM + 2 * kk;
        uint32_t wh[4], wl[4];
#pragma unroll
        for (int j = 0; j < 4; j++) {
            float2 w = *(const float2*)(src + (size_t)j * CDIM);
            pack_pair(w.x, w.y, wh[j], wl[j]);
        }
        *(uint4*)(W2h + kk * PW + r4) = *(uint4*)wh;
        *(uint4*)(W2l + kk * PW + r4) = *(uint4*)wl;
    }

    // ---- accum-phase ownership (unchanged FFMA scheme) ----
    const int hd = t >> 1;
    const int p  = t & 1;
    const int h  = hd >> 5;
    float Aacc[16];
#pragma unroll
    for (int i = 0; i < 16; i++) Aacc[i] = 0.f;
    float Sacc = 0.f;

    // ---- HMMA fragment geometry ----
    const int g  = lane >> 2;          // 0..7
    const int q  = lane & 3;           // 0..3
    const int R0 = wid * 32;           // warp rows R0..R0+31 of 256

    const float* xb = x + (size_t)b * CDIM * NSP + ch * CHUNK;

    __syncthreads();

    for (int s = 0; s < NSUB; s++) {
        // ---- B fill: x[c][n0s..+31] -> packed k-pair bf16 hi/lo (STS.128) ----
#pragma unroll
        for (int i = 0; i < 2; i++) {
            int li = t + i * 256;
            int kk = li >> 3;
            int n4 = (li & 7) * 4;
            const float* src = xb + (size_t)(2 * kk) * NSP + s * SUBN + n4;
            float4 a = *(const float4*)src;
            float4 c = *(const float4*)(src + NSP);
            uint32_t wh[4], wl[4];
            pack_pair(a.x, c.x, wh[0], wl[0]);
            pack_pair(a.y, c.y, wh[1], wl[1]);
            pack_pair(a.z, c.z, wh[2], wl[2]);
            pack_pair(a.w, c.w, wh[3], wl[3]);
            *(uint4*)(B2h + kk * PB + n4) = *(uint4*)wh;
            *(uint4*)(B2l + kk * PB + n4) = *(uint4*)wl;
        }
        __syncthreads();

        // ---- HMMA GEMM: warp tile 32x32, K=128, 3-term split ----
        float acc[2][4][4];
#pragma unroll
        for (int f = 0; f < 2; f++)
#pragma unroll
            for (int nf = 0; nf < 4; nf++)
#pragma unroll
                for (int j = 0; j < 4; j++) acc[f][nf][j] = 0.f;

#pragma unroll
        for (int kt = 0; kt < 8; kt++) {
            const int k0 = kt * 8;
            uint32_t ah[2][4], al[2][4], bh[4][2], bl[4][2];
#pragma unroll
            for (int f = 0; f < 2; f++) {
                int r = R0 + f * 16 + g;
                ah[f][0] = W2h[(k0 + q) * PW + r];
                ah[f][1] = W2h[(k0 + q) * PW + r + 8];
                ah[f][2] = W2h[(k0 + q + 4) * PW + r];
                ah[f][3] = W2h[(k0 + q + 4) * PW + r + 8];
                al[f][0] = W2l[(k0 + q) * PW + r];
                al[f][1] = W2l[(k0 + q) * PW + r + 8];
                al[f][2] = W2l[(k0 + q + 4) * PW + r];
                al[f][3] = W2l[(k0 + q + 4) * PW + r + 8];
            }
#pragma unroll
            for (int nf = 0; nf < 4; nf++) {
                int n = nf * 8 + g;
                bh[nf][0] = B2h[(k0 + q) * PB + n];
                bh[nf][1] = B2h[(k0 + q + 4) * PB + n];
                bl[nf][0] = B2l[(k0 + q) * PB + n];
                bl[nf][1] = B2l[(k0 + q + 4) * PB + n];
            }
#pragma unroll
            for (int f = 0; f < 2; f++)
#pragma unroll
                for (int nf = 0; nf < 4; nf++) {
                    mma16816(acc[f][nf], ah[f], bh[nf]);
                    mma16816(acc[f][nf], ah[f], bl[nf]);
                    mma16816(acc[f][nf], al[f], bh[nf]);
                }
        }

        // ---- scatter to ke (exp) / vsm (raw): rows 0..127 / 128..255 ----
        if (wid < 4) {
#pragma unroll
            for (int f = 0; f < 2; f++) {
                int r = R0 + f * 16 + g;
#pragma unroll
                for (int nf = 0; nf < 4; nf++) {
                    int nc = nf * 8 + 2 * q;
                    *(float2*)(ke + r * KPITCH + nc) =
                        {__expf(acc[f][nf][0]), __expf(acc[f][nf][1])};
                    *(float2*)(ke + (r + 8) * KPITCH + nc) =
                        {__expf(acc[f][nf][2]), __expf(acc[f][nf][3])};
                }
            }
        } else {
#pragma unroll
            for (int f = 0; f < 2; f++) {
                int r = R0 - 128 + f * 16 + g;
#pragma unroll
                for (int nf = 0; nf < 4; nf++) {
                    int nc = nf * 8 + 2 * q;
                    *(float2*)(vsm + r * KPITCH + nc) =
                        {acc[f][nf][0], acc[f][nf][1]};
                    *(float2*)(vsm + (r + 8) * KPITCH + nc) =
                        {acc[f][nf][2], acc[f][nf][3]};
                }
            }
        }
        __syncthreads();

        // ---- FFMA accum: A[hd][e] += ke[hd].vsm[h*32+e], S[hd] += sum ----
#pragma unroll
        for (int c4 = 0; c4 < SUBN; c4 += 4) {
            float4 kv = *(const float4*)(ke + hd * KPITCH + c4);
            if (p == 0) Sacc += (kv.x + kv.y) + (kv.z + kv.w);
#pragma unroll
            for (int i = 0; i < 16; i++) {
                float4 vv = *(const float4*)(vsm + (h * 32 + p * 16 + i) * KPITCH + c4);
                Aacc[i] += kv.x * vv.x + kv.y * vv.y + kv.z * vv.z + kv.w * vv.w;
            }
        }
        __syncthreads();
    }

    // ---- write partials ----
    float* pa = g_partA + ((size_t)(b * NCHUNKS + ch) * 128 + hd) * 32 + p * 16;
#pragma unroll
    for (int i = 0; i < 16; i++) pa[i] = Aacc[i];
    if (p == 0) g_partS[(b * NCHUNKS + ch) * 128 + hd] = Sacc;
}

// ---------------------------------------------------------------------------
// K2a: reduce partials -> ctx[b][hd][e] = A/S.
// ---------------------------------------------------------------------------
__global__ void k2_ctx() {
    int idx = blockIdx.x * blockDim.x + threadIdx.x;
    int b  = idx >> 12;
    int r  = idx & 4095;
    int hd = r >> 5;
    int e  = r & 31;
    float sA = 0.f, sS = 0.f;
    for (int chn = 0; chn < NCHUNKS; chn++) {
        sA += g_partA[((size_t)(b * NCHUNKS + chn) * 128 + hd) * 32 + e];
        sS += g_partS[(b * NCHUNKS + chn) * 128 + hd];
    }
    g_ctx[idx] = sA / sS;
}

// ---------------------------------------------------------------------------
// K2b: U[b][o][hd] = sum_e w_out[o][h*32+e] * ctx[b][hd][e].
// ---------------------------------------------------------------------------
__global__ void k2_u(const float* __restrict__ w_out) {
    int idx = blockIdx.x * blockDim.x + threadIdx.x;
    int b  = idx >> 14;
    int o  = (idx >> 7) & 127;
    int hd = idx & 127;
    int h  = hd >> 5;
    const float* wo = w_out + (size_t)o * 128 + h * 32;
    const float* cx = g_ctx + (size_t)b * 4096 + hd * 32;
    float acc = 0.f;
#pragma unroll
    for (int e = 0; e < 32; e++) acc += wo[e] * cx[e];
    g_U[idx] = acc;
}

// ---------------------------------------------------------------------------
// K2c: M[b][o][c] = scale * sum_hd U[b][o][hd] * w_qkv[hd][c].
// ---------------------------------------------------------------------------
__global__ void k2_m(const float* __restrict__ w_qkv) {
    int idx = blockIdx.x * blockDim.x + threadIdx.x;
    int b = idx >> 14;
    int o = (idx >> 7) & 127;
    int c = idx & 127;
    const float* U = g_U + ((size_t)b * 128 + o) * 128;
    float acc = 0.f;
#pragma unroll 8
    for (int hd = 0; hd < 128; hd++)
        acc += U[hd] * w_qkv[(size_t)hd * CDIM + c];
    g_M[idx] = 0.17677669529663687f * acc;   // 1/sqrt(32)
}

// ===========================================================================
// K3 (HMMA): final[b](128 x 16384) = M_b(128x128) @ x[b] + b_out.
// grid (128 n-tiles, BATCH), 256 threads, 1 CTA = 128x128 out tile.
// bf16 3-term split, STS.128 fills, pitch-136 conflict-free smem.
// ===========================================================================
#define K3_PITCH 136
#define K3_MAT_WORDS (64 * K3_PITCH)                 // 8704 words
#define K3_SMEM_BYTES (4 * K3_MAT_WORDS * 4)         // 139264 B

__global__ __launch_bounds__(256, 1) void k3_mm(const float* __restrict__ x,
                                                const float* __restrict__ b_out,
                                                float* __restrict__ out) {
    extern __shared__ uint32_t sm4[];
    uint32_t* A2h = sm4;
    uint32_t* A2l = sm4 + K3_MAT_WORDS;
    uint32_t* B2h = sm4 + 2 * K3_MAT_WORDS;
    uint32_t* B2l = sm4 + 3 * K3_MAT_WORDS;

    const int t    = threadIdx.x;
    const int wid  = t >> 5;
    const int lane = t & 31;
    const int b    = blockIdx.y;
    const int n0   = blockIdx.x * 128;

    // ---- A fill = M_b [o][c] -> A2[kk][o], 4 consecutive o per STS.128 ----
    {
        const float* Mg = g_M + (size_t)b * 16384;
#pragma unroll
        for (int i = 0; i < 8; i++) {
            int li = t + i * 256;            // 2048 tasks
            int kk = li >> 5;
            int o4 = (li & 31) * 4;
            const float* src = Mg + (size_t)o4 * 128 + 2 * kk;
            uint32_t wh[4], wl[4];
#pragma unroll
            for (int j = 0; j < 4; j++) {
                float2 v = *(const float2*)(src + (size_t)j * 128);
                pack_pair(v.x, v.y, wh[j], wl[j]);
            }
            *(uint4*)(A2h + kk * K3_PITCH + o4) = *(uint4*)wh;
            *(uint4*)(A2l + kk * K3_PITCH + o4) = *(uint4*)wl;
        }
    }

    // ---- B fill = x[c][n0..n0+127] -> B2[kk][n], STS.128 ----
    {
        const float* xb = x + (size_t)b * CDIM * NSP + n0;
#pragma unroll
        for (int i = 0; i < 8; i++) {
            int li = t + i * 256;            // 2048 tasks
            int kk = li >> 5;
            int n4 = (li & 31) * 4;
            const float* src = xb + (size_t)(2 * kk) * NSP + n4;
            float4 a = *(const float4*)src;
            float4 c = *(const float4*)(src + NSP);
            uint32_t wh[4], wl[4];
            pack_pair(a.x, c.x, wh[0], wl[0]);
            pack_pair(a.y, c.y, wh[1], wl[1]);
            pack_pair(a.z, c.z, wh[2], wl[2]);
            pack_pair(a.w, c.w, wh[3], wl[3]);
            *(uint4*)(B2h + kk * K3_PITCH + n4) = *(uint4*)wh;
            *(uint4*)(B2l + kk * K3_PITCH + n4) = *(uint4*)wl;
        }
    }
    __syncthreads();

    // ---- warp tiles: 4 (M) x 2 (N) warps -> 32x64 each ----
    const int g = lane >> 2;
    const int q = lane & 3;
    const int m0  = (wid >> 1) * 32;
    const int nb0 = (wid & 1) * 64;

    float acc[2][8][4];
#pragma unroll
    for (int f = 0; f < 2; f++)
#pragma unroll
        for (int nf = 0; nf < 8; nf++)
#pragma unroll
            for (int j = 0; j < 4; j++) acc[f][nf][j] = 0.f;

#pragma unroll
    for (int kt = 0; kt < 8; kt++) {
        const int k0 = kt * 8;
        uint32_t ah[2][4], al[2][4], bh[8][2], bl[8][2];
#pragma unroll
        for (int f = 0; f < 2; f++) {
            int r = m0 + f * 16 + g;
            ah[f][0] = A2h[(k0 + q) * K3_PITCH + r];
            ah[f][1] = A2h[(k0 + q) * K3_PITCH + r + 8];
            ah[f][2] = A2h[(k0 + q + 4) * K3_PITCH + r];
            ah[f][3] = A2h[(k0 + q + 4) * K3_PITCH + r + 8];
            al[f][0] = A2l[(k0 + q) * K3_PITCH + r];
            al[f][1] = A2l[(k0 + q) * K3_PITCH + r + 8];
            al[f][2] = A2l[(k0 + q + 4) * K3_PITCH + r];
            al[f][3] = A2l[(k0 + q + 4) * K3_PITCH + r + 8];
        }
#pragma unroll
        for (int nf = 0; nf < 8; nf++) {
            int n = nb0 + nf * 8 + g;
            bh[nf][0] = B2h[(k0 + q) * K3_PITCH + n];
            bh[nf][1] = B2h[(k0 + q + 4) * K3_PITCH + n];
            bl[nf][0] = B2l[(k0 + q) * K3_PITCH + n];
            bl[nf][1] = B2l[(k0 + q + 4) * K3_PITCH + n];
        }
#pragma unroll
        for (int f = 0; f < 2; f++)
#pragma unroll
            for (int nf = 0; nf < 8; nf++) {
                mma16816(acc[f][nf], ah[f], bh[nf]);
                mma16816(acc[f][nf], ah[f], bl[nf]);
                mma16816(acc[f][nf], al[f], bh[nf]);
            }
    }

    // ---- epilogue: bias + store ----
#pragma unroll
    for (int f = 0; f < 2; f++) {
        int r0 = m0 + f * 16 + g;
        float bias0 = __ldg(b_out + r0);
        float bias1 = __ldg(b_out + r0 + 8);
        float* o0 = out + ((size_t)b * CDIM + r0) * NSP + n0;
        float* o1 = o0 + 8 * NSP;
#pragma unroll
        for (int nf = 0; nf < 8; nf++) {
            int nc = nb0 + nf * 8 + q * 2;
            float2 v0 = {acc[f][nf][0] + bias0, acc[f][nf][1] + bias0};
            float2 v1 = {acc[f][nf][2] + bias1, acc[f][nf][3] + bias1};
            *(float2*)(o0 + nc) = v0;
            *(float2*)(o1 + nc) = v1;
        }
    }
}

// ---------------------------------------------------------------------------
extern "C" void kernel_launch(void* const* d_in, const int* in_sizes, int n_in,
                              void* d_out, int out_size) {
    const float* x     = (const float*)d_in[0];
    const float* w_qkv = (const float*)d_in[1];
    const float* w_out = (const float*)d_in[2];
    const float* b_out = (const float*)d_in[3];
    float* out = (float*)d_out;

    cudaFuncSetAttribute(k1_ctx, cudaFuncAttributeMaxDynamicSharedMemorySize,
                         K1_SMEM_BYTES);
    cudaFuncSetAttribute(k3_mm, cudaFuncAttributeMaxDynamicSharedMemorySize,
                         K3_SMEM_BYTES);

    k1_ctx<<<dim3(NCHUNKS, BATCH), 256, K1_SMEM_BYTES>>>(x, w_qkv);
    k2_ctx<<<256, 256>>>();
    k2_u<<<1024, 256>>>(w_out);
    k2_m<<<1024, 256>>>(w_qkv);
    k3_mm<<<dim3(NSP / 128, BATCH), 256, K3_SMEM_BYTES>>>(x, b_out, out);
}